// round 8
// baseline (speedup 1.0000x reference)
#include <cuda_runtime.h>
#include <cuda_bf16.h>
#include <cstdint>

#define Bb 32
#define Ss 4096
#define Hh 512
#define Ee 512
#define NEGV -1000000000.0f

// ---------------- scratch ----------------
__device__ float g_qpc[Bb * Hh];
__device__ float g_ctxpart[16 * Bb * Ee];
__device__ __align__(16) __nv_bfloat16 g_wkt_hi[Hh * Ee];   // Wk^T hi [h][e]
__device__ __align__(16) __nv_bfloat16 g_wkt_lo[Hh * Ee];   // Wk^T lo [h][e]

// ---------------- helpers ----------------
__device__ __forceinline__ uint32_t smem_u32(const void* p) {
    uint32_t a;
    asm("{ .reg .u64 t; cvta.to.shared.u64 t, %1; cvt.u32.u64 %0, t; }" : "=r"(a) : "l"(p));
    return a;
}
__device__ __forceinline__ uint32_t swz(uint32_t off) { return off ^ ((off >> 3) & 0x70); }

__device__ __forceinline__ float tanh_fast(float x) {
    float e = __expf(2.0f * x);
    return 1.0f - __fdividef(2.0f, e + 1.0f);
}
__device__ __forceinline__ void ldmx4(uint32_t& r0, uint32_t& r1, uint32_t& r2, uint32_t& r3,
                                      uint32_t addr) {
    asm volatile("ldmatrix.sync.aligned.m8n8.x4.shared.b16 {%0,%1,%2,%3}, [%4];"
                 : "=r"(r0), "=r"(r1), "=r"(r2), "=r"(r3) : "r"(addr));
}
__device__ __forceinline__ void mma16816(float* d, const uint32_t* a, uint32_t b0, uint32_t b1) {
    asm volatile(
        "mma.sync.aligned.m16n8k16.row.col.f32.bf16.bf16.f32 "
        "{%0,%1,%2,%3}, {%4,%5,%6,%7}, {%8,%9}, {%0,%1,%2,%3};"
        : "+f"(d[0]), "+f"(d[1]), "+f"(d[2]), "+f"(d[3])
        : "r"(a[0]), "r"(a[1]), "r"(a[2]), "r"(a[3]), "r"(b0), "r"(b1));
}
#define CP_ASYNC16(dst, src) \
    asm volatile("cp.async.cg.shared.global [%0], [%1], 16;" :: "r"(dst), "l"(src))
#define CP_COMMIT() asm volatile("cp.async.commit_group;" ::: "memory")
#define CP_WAIT0() asm volatile("cp.async.wait_group 0;" ::: "memory")

// ---------------- K0: transpose+convert Wk -> bf16 hi/lo (Wkt[h][e]) ----------------
__global__ void wkt_kernel(const float* __restrict__ Wk) {
    __shared__ float t[64][65];
    int e0 = (blockIdx.x >> 3) * 64, h0 = (blockIdx.x & 7) * 64;
    int tx = threadIdx.x & 63, ty = threadIdx.x >> 6;
#pragma unroll
    for (int i = 0; i < 16; i++) {
        int r = ty + i * 4;
        t[r][tx] = Wk[(size_t)(e0 + r) * Hh + h0 + tx];
    }
    __syncthreads();
#pragma unroll
    for (int i = 0; i < 16; i++) {
        int hr = ty + i * 4;
        float x = t[tx][hr];
        __nv_bfloat16 hi = __float2bfloat16(x);
        __nv_bfloat16 lo = __float2bfloat16(x - __bfloat162float(hi));
        g_wkt_hi[(size_t)(h0 + hr) * Ee + e0 + tx] = hi;
        g_wkt_lo[(size_t)(h0 + hr) * Ee + e0 + tx] = lo;
    }
}

// ---------------- K1: q_proj + bq + bk (128 blocks) ----------------
__global__ void qproj_kernel(const float* __restrict__ query, const float* __restrict__ Wq,
                             const float* __restrict__ bq, const float* __restrict__ bk) {
    __shared__ float qs[Hh];
    int b = blockIdx.x >> 2;
    int h = (blockIdx.x & 3) * 128 + threadIdx.x;
#pragma unroll
    for (int i = 0; i < 4; i++) qs[threadIdx.x + i * 128] = query[b * Hh + threadIdx.x + i * 128];
    __syncthreads();
    float acc = bq[h] + bk[h];
#pragma unroll 8
    for (int e = 0; e < Hh; e++) acc += qs[e] * Wq[e * Hh + h];
    g_qpc[b * Hh + h] = acc;
}

// ---------------- K2: mma.sync scores kernel ----------------
// CTA: M=128 x H via 4 N-phases of 128. 8 warps = 4(M) x 2(N), warp tile m32n64.
// A: LDG->regs->cvt->STS (one chunk ahead). B: cp.async (one chunk ahead).
// One __syncthreads per iteration.
#define MT 128
#define NP 128
#define KC 64
#define NIT 32                    // 4 phases x 8 k-chunks
#define O_A 0                     // 2 x (Ah 16K | Al 16K)
#define O_B 65536                 // 2 x (Bh 16K | Bl 16K)
#define O_SQ 131072
#define O_SV (O_SQ + 2048)
#define O_RED (O_SV + 2048)
#define SMEM_TOTAL (O_RED + 1024)

__device__ __forceinline__ void issue_cpB(uint32_t smem_base, int it) {
    const int tid = threadIdx.x;
    const int p = it >> 3, kc = it & 7;
    const int st = it & 1;
    const uint32_t bh = smem_base + O_B + st * 32768;
    const uint32_t bl = bh + 16384;
#pragma unroll
    for (int j = 0; j < 4; j++) {
        int s = tid + j * 256;
        int n = s >> 3, k8 = (s & 7) * 8;
        size_t gidx = (size_t)(p * NP + n) * Ee + kc * KC + k8;
        uint32_t off = swz((uint32_t)(n * 128 + k8 * 2));
        CP_ASYNC16(bh + off, (const char*)(g_wkt_hi + gidx));
        CP_ASYNC16(bl + off, (const char*)(g_wkt_lo + gidx));
    }
}

// Each thread owns row r = tid/2, k-half kh = tid&1 (32 floats).
__device__ __forceinline__ void ldgA(const float* __restrict__ keys, int row0, int it,
                                     float4* buf) {
    const int r = threadIdx.x >> 1;
    const int kh = threadIdx.x & 1;
    const int kc = it & 7;
    const float* ap = keys + (size_t)(row0 + r) * Ee + kc * KC + kh * 32;
#pragma unroll
    for (int i = 0; i < 8; i++) buf[i] = *(const float4*)(ap + i * 4);
}

__device__ __forceinline__ void cvtA_store(char* smem, int it, const float4* buf) {
    const int r = threadIdx.x >> 1;
    const int kh = threadIdx.x & 1;
    const int st = it & 1;
    char* Ah = smem + O_A + st * 32768;
    char* Al = Ah + 16384;
#pragma unroll
    for (int g = 0; g < 4; g++) {
        float xs[8] = {buf[g * 2].x,     buf[g * 2].y,     buf[g * 2].z,     buf[g * 2].w,
                       buf[g * 2 + 1].x, buf[g * 2 + 1].y, buf[g * 2 + 1].z, buf[g * 2 + 1].w};
        union { uint4 u; __nv_bfloat16 b[8]; } vh, vl;
#pragma unroll
        for (int i = 0; i < 8; i++) {
            __nv_bfloat16 h = __float2bfloat16(xs[i]);
            vh.b[i] = h;
            vl.b[i] = __float2bfloat16(xs[i] - __bfloat162float(h));
        }
        uint32_t off = swz((uint32_t)(r * 128 + (kh * 32 + g * 8) * 2));
        *(uint4*)(Ah + off) = vh.u;
        *(uint4*)(Al + off) = vl.u;
    }
}

__global__ __launch_bounds__(256, 1) void scores_mma_kernel(
    const float* __restrict__ keys, const int* __restrict__ mask,
    const float* __restrict__ v, const float* __restrict__ bv,
    float* __restrict__ scores) {
    extern __shared__ char smem[];
    const uint32_t smem_base = smem_u32(smem);
    const int tid = threadIdx.x;
    const int lane = tid & 31;
    const int wid = tid >> 5;
    const int wm = wid >> 1;          // 0..3
    const int wn = wid & 1;           // 0..1
    const int m_off = wm * 32;
    const int n_off = wn * 64;
    const int row0 = blockIdx.x * MT;
    const int b = row0 >> 12;

    float* sq = (float*)(smem + O_SQ);
    float* sv = (float*)(smem + O_SV);
    sq[tid] = g_qpc[b * Hh + tid];
    sq[tid + 256] = g_qpc[b * Hh + tid + 256];
    sv[tid] = v[tid];
    sv[tid + 256] = v[tid + 256];

    const int jm = lane >> 3;
    const int rr = lane & 7;

    float rs[4] = {0.f, 0.f, 0.f, 0.f};
    float acc[2][8][4];
#pragma unroll
    for (int f = 0; f < 2; f++)
#pragma unroll
        for (int j = 0; j < 8; j++)
#pragma unroll
            for (int q = 0; q < 4; q++) acc[f][j][q] = 0.f;

    float4 abuf[8];

    // prologue: stage chunk 0
    issue_cpB(smem_base, 0);
    CP_COMMIT();
    ldgA(keys, row0, 0, abuf);
    cvtA_store(smem, 0, abuf);
    CP_WAIT0();
    __syncthreads();

    for (int it = 0; it < NIT; it++) {
        const int p = it >> 3, kc = it & 7;
        const int st = it & 1;
        const uint32_t ah_base = smem_base + O_A + st * 32768;
        const uint32_t al_base = ah_base + 16384;
        const uint32_t bh_base = smem_base + O_B + st * 32768;
        const uint32_t bl_base = bh_base + 16384;

        // prefetch next chunk: B via cp.async, A via LDG (latency hidden by MMAs)
        if (it + 1 < NIT) {
            issue_cpB(smem_base, it + 1);
            ldgA(keys, row0, it + 1, abuf);
        }
        CP_COMMIT();

        // ---- MMAs on chunk it ----
#pragma unroll
        for (int kk = 0; kk < 4; kk++) {
            const int k0l = kk * 16;
            uint32_t ahi[2][4], alo[2][4];
#pragma unroll
            for (int f = 0; f < 2; f++) {
                uint32_t aoff = swz((uint32_t)((m_off + f * 16 + (jm & 1) * 8 + rr) * 128 +
                                               (k0l + (jm >> 1) * 8) * 2));
                ldmx4(ahi[f][0], ahi[f][1], ahi[f][2], ahi[f][3], ah_base + aoff);
                ldmx4(alo[f][0], alo[f][1], alo[f][2], alo[f][3], al_base + aoff);
            }
#pragma unroll
            for (int q = 0; q < 4; q++) {
                const int frag0 = 2 * q;
                uint32_t boff = swz((uint32_t)((n_off + (frag0 + (jm >> 1)) * 8 + rr) * 128 +
                                               (k0l + (jm & 1) * 8) * 2));
                uint32_t bh0, bh1, bh2, bh3, bl0, bl1, bl2, bl3;
                ldmx4(bh0, bh1, bh2, bh3, bh_base + boff);
                ldmx4(bl0, bl1, bl2, bl3, bl_base + boff);
#pragma unroll
                for (int f = 0; f < 2; f++) {
                    mma16816(acc[f][frag0], ahi[f], bh0, bh1);
                    mma16816(acc[f][frag0], ahi[f], bl0, bl1);
                    mma16816(acc[f][frag0], alo[f], bh0, bh1);
                    mma16816(acc[f][frag0 + 1], ahi[f], bh2, bh3);
                    mma16816(acc[f][frag0 + 1], ahi[f], bl2, bl3);
                    mma16816(acc[f][frag0 + 1], alo[f], bh2, bh3);
                }
            }
        }

        // convert prefetched A into stage st^1 (written only by this thread; no race)
        if (it + 1 < NIT) cvtA_store(smem, it + 1, abuf);

        CP_WAIT0();          // B(it+1) arrived
        __syncthreads();     // one barrier per iter: STS + cp.async visible, stage handoff

        // ---- end of phase: fold accumulators into row sums ----
        if (kc == 7) {
#pragma unroll
            for (int f = 0; f < 2; f++)
#pragma unroll
                for (int j = 0; j < 8; j++) {
                    const int col = p * NP + n_off + j * 8 + (lane & 3) * 2;
                    const float q0 = sq[col], q1 = sq[col + 1];
                    const float v0 = sv[col], v1 = sv[col + 1];
                    rs[f * 2 + 0] += tanh_fast(acc[f][j][0] + q0) * v0 +
                                     tanh_fast(acc[f][j][1] + q1) * v1;
                    rs[f * 2 + 1] += tanh_fast(acc[f][j][2] + q0) * v0 +
                                     tanh_fast(acc[f][j][3] + q1) * v1;
                    acc[f][j][0] = acc[f][j][1] = acc[f][j][2] = acc[f][j][3] = 0.f;
                }
        }
    }

    // reduce across 4 lanes sharing a row, then across 2 N-warps
#pragma unroll
    for (int i = 0; i < 4; i++) {
        rs[i] += __shfl_xor_sync(~0u, rs[i], 1);
        rs[i] += __shfl_xor_sync(~0u, rs[i], 2);
    }
    float* red = (float*)(smem + O_RED);   // [128][2]
    if ((lane & 3) == 0) {
#pragma unroll
        for (int i = 0; i < 4; i++) {
            int r = m_off + (i >> 1) * 16 + (i & 1) * 8 + (lane >> 2);
            red[r * 2 + wn] = rs[i];
        }
    }
    __syncthreads();
    if (tid < MT) {
        float s = red[tid * 2] + red[tid * 2 + 1] + bv[0];
        int grow = row0 + tid;
        s = (mask[grow] == 0) ? NEGV : s;
        scores[grow] = s;
    }
}

// ---------------- K3: softmax ----------------
__global__ void softmax_kernel(float* __restrict__ attn) {
    __shared__ float buf[Ss];
    __shared__ float rtmp[32];
    __shared__ float rowstat;
    int b = blockIdx.x, tid = threadIdx.x;
    float* row = attn + (size_t)b * Ss;
    float lmax = -3.4e38f;
#pragma unroll
    for (int i = 0; i < Ss / 256; i++) {
        float x = row[tid + i * 256];
        buf[tid + i * 256] = x;
        lmax = fmaxf(lmax, x);
    }
#pragma unroll
    for (int o = 16; o; o >>= 1) lmax = fmaxf(lmax, __shfl_xor_sync(~0u, lmax, o));
    if ((tid & 31) == 0) rtmp[tid >> 5] = lmax;
    __syncthreads();
    if (tid == 0) {
        float m = rtmp[0];
        for (int w = 1; w < 8; w++) m = fmaxf(m, rtmp[w]);
        rowstat = m;
    }
    __syncthreads();
    float m = rowstat;
    float lsum = 0.0f;
#pragma unroll
    for (int i = 0; i < Ss / 256; i++) {
        float e = __expf(buf[tid + i * 256] - m);
        buf[tid + i * 256] = e;
        lsum += e;
    }
#pragma unroll
    for (int o = 16; o; o >>= 1) lsum += __shfl_xor_sync(~0u, lsum, o);
    __syncthreads();
    if ((tid & 31) == 0) rtmp[tid >> 5] = lsum;
    __syncthreads();
    if (tid == 0) {
        float s = 0.0f;
        for (int w = 0; w < 8; w++) s += rtmp[w];
        rowstat = 1.0f / s;
    }
    __syncthreads();
    float inv = rowstat;
#pragma unroll
    for (int i = 0; i < Ss / 256; i++) row[tid + i * 256] = buf[tid + i * 256] * inv;
}

// ---------------- K4/K5: context ----------------
__global__ void context_partial_kernel(const float* __restrict__ keys,
                                       const float* __restrict__ attn) {
    __shared__ float aw[256];
    int b = blockIdx.y, chunk = blockIdx.x;   // 16 chunks of 256
    int s0 = chunk * 256;
    int tid = threadIdx.x;                    // 512
    if (tid < 256) aw[tid] = attn[(size_t)b * Ss + s0 + tid];
    __syncthreads();
    const float* kp = keys + ((size_t)b * Ss + s0) * Ee + tid;
    float acc = 0.0f;
#pragma unroll 8
    for (int s = 0; s < 256; s++) acc += aw[s] * kp[(size_t)s * Ee];
    g_ctxpart[(chunk * Bb + b) * Ee + tid] = acc;
}

__global__ void context_reduce_kernel(float* __restrict__ ctx) {
    int b = blockIdx.x, e = threadIdx.x;
    float acc = 0.0f;
#pragma unroll
    for (int c = 0; c < 16; c++) acc += g_ctxpart[(c * Bb + b) * Ee + e];
    ctx[b * Ee + e] = acc;
}

extern "C" void kernel_launch(void* const* d_in, const int* in_sizes, int n_in,
                              void* d_out, int out_size) {
    const float* query = (const float*)d_in[0];
    const float* keys  = (const float*)d_in[1];
    const int*   mask  = (const int*)d_in[2];
    const float* Wq    = (const float*)d_in[3];
    const float* bq    = (const float*)d_in[4];
    const float* Wk    = (const float*)d_in[5];
    const float* bk    = (const float*)d_in[6];
    const float* v     = (const float*)d_in[7];
    const float* bv    = (const float*)d_in[8];

    float* out  = (float*)d_out;
    float* ctx  = out;
    float* attn = out + Bb * Ee;

    cudaFuncSetAttribute(scores_mma_kernel, cudaFuncAttributeMaxDynamicSharedMemorySize,
                         SMEM_TOTAL);

    wkt_kernel<<<64, 256>>>(Wk);
    qproj_kernel<<<Bb * 4, 128>>>(query, Wq, bq, bk);
    scores_mma_kernel<<<(Bb * Ss) / MT, 256, SMEM_TOTAL>>>(keys, mask, v, bv, attn);
    softmax_kernel<<<Bb, 256>>>(attn);
    {
        dim3 grid(16, Bb);
        context_partial_kernel<<<grid, 512>>>(keys, attn);
    }
    context_reduce_kernel<<<Bb, Ee>>>(ctx);
}

// round 9
// speedup vs baseline: 1.4233x; 1.4233x over previous
#include <cuda_runtime.h>
#include <cuda_fp16.h>
#include <cstdint>

#define Bb 32
#define Ss 4096
#define Hh 512
#define Ee 512
#define NEGV -1000000000.0f

// ---------------- scratch ----------------
__device__ float g_qpc[Bb * Hh];
__device__ float g_ctxpart[16 * Bb * Ee];
__device__ __align__(16) __half g_wkt_hi[Hh * Ee];   // Wk^T hi [h][e] fp16
__device__ __align__(16) __half g_wkt_lo[Hh * Ee];   // Wk^T lo [h][e] fp16

// ---------------- helpers ----------------
__device__ __forceinline__ uint32_t smem_u32(const void* p) {
    uint32_t a;
    asm("{ .reg .u64 t; cvta.to.shared.u64 t, %1; cvt.u32.u64 %0, t; }" : "=r"(a) : "l"(p));
    return a;
}
__device__ __forceinline__ uint32_t swz(uint32_t off) { return off ^ ((off >> 3) & 0x70); }

__device__ __forceinline__ float tanh_fast(float x) {
    float e = __expf(2.0f * x);
    return 1.0f - __fdividef(2.0f, e + 1.0f);
}
__device__ __forceinline__ void ldmx4(uint32_t& r0, uint32_t& r1, uint32_t& r2, uint32_t& r3,
                                      uint32_t addr) {
    asm volatile("ldmatrix.sync.aligned.m8n8.x4.shared.b16 {%0,%1,%2,%3}, [%4];"
                 : "=r"(r0), "=r"(r1), "=r"(r2), "=r"(r3) : "r"(addr));
}
__device__ __forceinline__ void mma16816(float* d, const uint32_t* a, uint32_t b0, uint32_t b1) {
    asm volatile(
        "mma.sync.aligned.m16n8k16.row.col.f32.f16.f16.f32 "
        "{%0,%1,%2,%3}, {%4,%5,%6,%7}, {%8,%9}, {%0,%1,%2,%3};"
        : "+f"(d[0]), "+f"(d[1]), "+f"(d[2]), "+f"(d[3])
        : "r"(a[0]), "r"(a[1]), "r"(a[2]), "r"(a[3]), "r"(b0), "r"(b1));
}
#define CP_ASYNC16(dst, src) \
    asm volatile("cp.async.cg.shared.global [%0], [%1], 16;" :: "r"(dst), "l"(src))
#define CP_COMMIT() asm volatile("cp.async.commit_group;" ::: "memory")
#define CP_WAIT1() asm volatile("cp.async.wait_group 1;" ::: "memory")

// ---------------- K0: transpose+convert Wk -> fp16 hi/lo (Wkt[h][e]) ----------------
__global__ void wkt_kernel(const float* __restrict__ Wk) {
    __shared__ float t[64][65];
    int e0 = (blockIdx.x >> 3) * 64, h0 = (blockIdx.x & 7) * 64;
    int tx = threadIdx.x & 63, ty = threadIdx.x >> 6;
#pragma unroll
    for (int i = 0; i < 16; i++) {
        int r = ty + i * 4;
        t[r][tx] = Wk[(size_t)(e0 + r) * Hh + h0 + tx];
    }
    __syncthreads();
#pragma unroll
    for (int i = 0; i < 16; i++) {
        int hr = ty + i * 4;
        float x = t[tx][hr];
        __half hi = __float2half(x);
        __half lo = __float2half(x - __half2float(hi));
        g_wkt_hi[(size_t)(h0 + hr) * Ee + e0 + tx] = hi;
        g_wkt_lo[(size_t)(h0 + hr) * Ee + e0 + tx] = lo;
    }
}

// ---------------- K1: q_proj + bq + bk (128 blocks) ----------------
__global__ void qproj_kernel(const float* __restrict__ query, const float* __restrict__ Wq,
                             const float* __restrict__ bq, const float* __restrict__ bk) {
    __shared__ float qs[Hh];
    int b = blockIdx.x >> 2;
    int h = (blockIdx.x & 3) * 128 + threadIdx.x;
#pragma unroll
    for (int i = 0; i < 4; i++) qs[threadIdx.x + i * 128] = query[b * Hh + threadIdx.x + i * 128];
    __syncthreads();
    float acc = bq[h] + bk[h];
#pragma unroll 8
    for (int e = 0; e < Hh; e++) acc += qs[e] * Wq[e * Hh + h];
    g_qpc[b * Hh + h] = acc;
}

// ---------------- K2: mma.sync scores kernel (fp16 2-MMA split) ----------------
// CTA: M=128 x H via 4 N-phases of 128. 8 warps = 4(M) x 2(N), warp tile m32n64.
// A: cp.async raw fp32, converted smem->smem to SINGLE fp16 one chunk ahead.
// B: cp.async pre-split fp16 hi/lo. kp = ah*bh + ah*bl.
#define MT 128
#define NP 128
#define KC 64
#define NIT 32                    // 4 phases x 8 k-chunks
#define O_ARAW 0                  // 2 x 32KB raw fp32 A
#define O_ACV 65536               // 2 x 16KB fp16 A
#define O_B 98304                 // 2 x (Bh 16K | Bl 16K)
#define O_SQ 163840
#define O_SV (O_SQ + 2048)
#define O_RED (O_SV + 2048)
#define SMEM_TOTAL (O_RED + 1024)

__device__ __forceinline__ void issue_cp(uint32_t smem_base, const float* __restrict__ keys,
                                         int row0, int it) {
    const int tid = threadIdx.x;
    const int p = it >> 3, kc = it & 7;
    const int st = it & 1;
    const uint32_t araw = smem_base + O_ARAW + st * 32768;
    const uint32_t bh = smem_base + O_B + st * 32768;
    const uint32_t bl = bh + 16384;
    // raw A: 128 rows x 64 fp32 = 2048 x 16B, 8/thread
#pragma unroll
    for (int j = 0; j < 8; j++) {
        int s = tid + j * 256;
        int r = s >> 4, kq = (s & 15) * 4;
        const char* src = (const char*)(keys + (size_t)(row0 + r) * Ee + kc * KC + kq);
        CP_ASYNC16(araw + r * 256 + kq * 4, src);
    }
    // B: 128 n x 64 k fp16 hi/lo, 1024 x 16B each, 4/thread each
#pragma unroll
    for (int j = 0; j < 4; j++) {
        int s = tid + j * 256;
        int n = s >> 3, k8 = (s & 7) * 8;
        size_t gidx = (size_t)(p * NP + n) * Ee + kc * KC + k8;
        uint32_t off = swz((uint32_t)(n * 128 + k8 * 2));
        CP_ASYNC16(bh + off, (const char*)(g_wkt_hi + gidx));
        CP_ASYNC16(bl + off, (const char*)(g_wkt_lo + gidx));
    }
}

__device__ __forceinline__ void convert_A(char* smem, int it) {
    const int tid = threadIdx.x;
    const int st = it & 1;
    const char* raw = smem + O_ARAW + st * 32768;
    char* Ac = smem + O_ACV + st * 16384;
    // 1024 segments of 8 fp16 (16B); 4 per thread
#pragma unroll
    for (int j = 0; j < 4; j++) {
        int s = tid + j * 256;
        int r = s >> 3, k8 = (s & 7) * 8;
        const float4* rp = (const float4*)(raw + r * 256 + k8 * 4);
        float4 x0 = rp[0], x1 = rp[1];
        union { uint4 u; __half b[8]; } vc;
        vc.b[0] = __float2half(x0.x); vc.b[1] = __float2half(x0.y);
        vc.b[2] = __float2half(x0.z); vc.b[3] = __float2half(x0.w);
        vc.b[4] = __float2half(x1.x); vc.b[5] = __float2half(x1.y);
        vc.b[6] = __float2half(x1.z); vc.b[7] = __float2half(x1.w);
        uint32_t off = swz((uint32_t)(r * 128 + k8 * 2));
        *(uint4*)(Ac + off) = vc.u;
    }
}

__global__ __launch_bounds__(256, 1) void scores_mma_kernel(
    const float* __restrict__ keys, const int* __restrict__ mask,
    const float* __restrict__ v, const float* __restrict__ bv,
    float* __restrict__ scores) {
    extern __shared__ char smem[];
    const uint32_t smem_base = smem_u32(smem);
    const int tid = threadIdx.x;
    const int lane = tid & 31;
    const int wid = tid >> 5;
    const int wm = wid >> 1;          // 0..3
    const int wn = wid & 1;           // 0..1
    const int m_off = wm * 32;
    const int n_off = wn * 64;
    const int row0 = blockIdx.x * MT;
    const int b = row0 >> 12;

    float* sq = (float*)(smem + O_SQ);
    float* sv = (float*)(smem + O_SV);
    sq[tid] = g_qpc[b * Hh + tid];
    sq[tid + 256] = g_qpc[b * Hh + tid + 256];
    sv[tid] = v[tid];
    sv[tid + 256] = v[tid + 256];

    const int jm = lane >> 3;
    const int rr = lane & 7;

    float rs[4] = {0.f, 0.f, 0.f, 0.f};
    float acc[2][8][4];
#pragma unroll
    for (int f = 0; f < 2; f++)
#pragma unroll
        for (int j = 0; j < 8; j++)
#pragma unroll
            for (int q = 0; q < 4; q++) acc[f][j][q] = 0.f;

    // prologue: load chunk 0 and 1; convert chunk 0
    issue_cp(smem_base, keys, row0, 0);
    CP_COMMIT();
    issue_cp(smem_base, keys, row0, 1);
    CP_COMMIT();
    CP_WAIT1();
    __syncthreads();
    convert_A(smem, 0);
    __syncthreads();

    for (int it = 0; it < NIT; it++) {
        const int p = it >> 3, kc = it & 7;
        const int st = it & 1;
        const uint32_t a_base = smem_base + O_ACV + st * 16384;
        const uint32_t bh_base = smem_base + O_B + st * 32768;
        const uint32_t bl_base = bh_base + 16384;

        // ---- MMAs on chunk it ----
#pragma unroll
        for (int kk = 0; kk < 4; kk++) {
            const int k0l = kk * 16;
            uint32_t af[2][4];
#pragma unroll
            for (int f = 0; f < 2; f++) {
                uint32_t aoff = swz((uint32_t)((m_off + f * 16 + (jm & 1) * 8 + rr) * 128 +
                                               (k0l + (jm >> 1) * 8) * 2));
                ldmx4(af[f][0], af[f][1], af[f][2], af[f][3], a_base + aoff);
            }
#pragma unroll
            for (int q = 0; q < 4; q++) {
                const int frag0 = 2 * q;
                uint32_t boff = swz((uint32_t)((n_off + (frag0 + (jm >> 1)) * 8 + rr) * 128 +
                                               (k0l + (jm & 1) * 8) * 2));
                uint32_t bh0, bh1, bh2, bh3, bl0, bl1, bl2, bl3;
                ldmx4(bh0, bh1, bh2, bh3, bh_base + boff);
                ldmx4(bl0, bl1, bl2, bl3, bl_base + boff);
#pragma unroll
                for (int f = 0; f < 2; f++) {
                    mma16816(acc[f][frag0], af[f], bh0, bh1);
                    mma16816(acc[f][frag0], af[f], bl0, bl1);
                    mma16816(acc[f][frag0 + 1], af[f], bh2, bh3);
                    mma16816(acc[f][frag0 + 1], af[f], bl2, bl3);
                }
            }
        }
        __syncthreads();                      // all warps done reading stage st

        // ---- issue loads for chunk it+2 into stage st ----
        if (it + 2 < NIT) issue_cp(smem_base, keys, row0, it + 2);
        CP_COMMIT();

        // ---- wait chunk it+1 arrival; convert its A ----
        if (it + 1 < NIT) {
            CP_WAIT1();
            __syncthreads();
            convert_A(smem, it + 1);
        }
        __syncthreads();

        // ---- end of phase: fold accumulators into row sums ----
        if (kc == 7) {
#pragma unroll
            for (int f = 0; f < 2; f++)
#pragma unroll
                for (int j = 0; j < 8; j++) {
                    const int col = p * NP + n_off + j * 8 + (lane & 3) * 2;
                    const float q0 = sq[col], q1 = sq[col + 1];
                    const float v0 = sv[col], v1 = sv[col + 1];
                    rs[f * 2 + 0] += tanh_fast(acc[f][j][0] + q0) * v0 +
                                     tanh_fast(acc[f][j][1] + q1) * v1;
                    rs[f * 2 + 1] += tanh_fast(acc[f][j][2] + q0) * v0 +
                                     tanh_fast(acc[f][j][3] + q1) * v1;
                    acc[f][j][0] = acc[f][j][1] = acc[f][j][2] = acc[f][j][3] = 0.f;
                }
        }
    }

    // reduce across 4 lanes sharing a row, then across 2 N-warps
#pragma unroll
    for (int i = 0; i < 4; i++) {
        rs[i] += __shfl_xor_sync(~0u, rs[i], 1);
        rs[i] += __shfl_xor_sync(~0u, rs[i], 2);
    }
    float* red = (float*)(smem + O_RED);   // [128][2]
    if ((lane & 3) == 0) {
#pragma unroll
        for (int i = 0; i < 4; i++) {
            int r = m_off + (i >> 1) * 16 + (i & 1) * 8 + (lane >> 2);
            red[r * 2 + wn] = rs[i];
        }
    }
    __syncthreads();
    if (tid < MT) {
        float s = red[tid * 2] + red[tid * 2 + 1] + bv[0];
        int grow = row0 + tid;
        s = (mask[grow] == 0) ? NEGV : s;
        scores[grow] = s;
    }
}

// ---------------- K3: softmax ----------------
__global__ void softmax_kernel(float* __restrict__ attn) {
    __shared__ float buf[Ss];
    __shared__ float rtmp[32];
    __shared__ float rowstat;
    int b = blockIdx.x, tid = threadIdx.x;
    float* row = attn + (size_t)b * Ss;
    float lmax = -3.4e38f;
#pragma unroll
    for (int i = 0; i < Ss / 256; i++) {
        float x = row[tid + i * 256];
        buf[tid + i * 256] = x;
        lmax = fmaxf(lmax, x);
    }
#pragma unroll
    for (int o = 16; o; o >>= 1) lmax = fmaxf(lmax, __shfl_xor_sync(~0u, lmax, o));
    if ((tid & 31) == 0) rtmp[tid >> 5] = lmax;
    __syncthreads();
    if (tid == 0) {
        float m = rtmp[0];
        for (int w = 1; w < 8; w++) m = fmaxf(m, rtmp[w]);
        rowstat = m;
    }
    __syncthreads();
    float m = rowstat;
    float lsum = 0.0f;
#pragma unroll
    for (int i = 0; i < Ss / 256; i++) {
        float e = __expf(buf[tid + i * 256] - m);
        buf[tid + i * 256] = e;
        lsum += e;
    }
#pragma unroll
    for (int o = 16; o; o >>= 1) lsum += __shfl_xor_sync(~0u, lsum, o);
    __syncthreads();
    if ((tid & 31) == 0) rtmp[tid >> 5] = lsum;
    __syncthreads();
    if (tid == 0) {
        float s = 0.0f;
        for (int w = 0; w < 8; w++) s += rtmp[w];
        rowstat = 1.0f / s;
    }
    __syncthreads();
    float inv = rowstat;
#pragma unroll
    for (int i = 0; i < Ss / 256; i++) row[tid + i * 256] = buf[tid + i * 256] * inv;
}

// ---------------- K4/K5: context ----------------
__global__ void context_partial_kernel(const float* __restrict__ keys,
                                       const float* __restrict__ attn) {
    __shared__ float aw[256];
    int b = blockIdx.y, chunk = blockIdx.x;   // 16 chunks of 256
    int s0 = chunk * 256;
    int tid = threadIdx.x;                    // 512
    if (tid < 256) aw[tid] = attn[(size_t)b * Ss + s0 + tid];
    __syncthreads();
    const float* kp = keys + ((size_t)b * Ss + s0) * Ee + tid;
    float acc = 0.0f;
#pragma unroll 8
    for (int s = 0; s < 256; s++) acc += aw[s] * kp[(size_t)s * Ee];
    g_ctxpart[(chunk * Bb + b) * Ee + tid] = acc;
}

__global__ void context_reduce_kernel(float* __restrict__ ctx) {
    int b = blockIdx.x, e = threadIdx.x;
    float acc = 0.0f;
#pragma unroll
    for (int c = 0; c < 16; c++) acc += g_ctxpart[(c * Bb + b) * Ee + e];
    ctx[b * Ee + e] = acc;
}

extern "C" void kernel_launch(void* const* d_in, const int* in_sizes, int n_in,
                              void* d_out, int out_size) {
    const float* query = (const float*)d_in[0];
    const float* keys  = (const float*)d_in[1];
    const int*   mask  = (const int*)d_in[2];
    const float* Wq    = (const float*)d_in[3];
    const float* bq    = (const float*)d_in[4];
    const float* Wk    = (const float*)d_in[5];
    const float* bk    = (const float*)d_in[6];
    const float* v     = (const float*)d_in[7];
    const float* bv    = (const float*)d_in[8];

    float* out  = (float*)d_out;
    float* ctx  = out;
    float* attn = out + Bb * Ee;

    cudaFuncSetAttribute(scores_mma_kernel, cudaFuncAttributeMaxDynamicSharedMemorySize,
                         SMEM_TOTAL);

    wkt_kernel<<<64, 256>>>(Wk);
    qproj_kernel<<<Bb * 4, 128>>>(query, Wq, bq, bk);
    scores_mma_kernel<<<(Bb * Ss) / MT, 256, SMEM_TOTAL>>>(keys, mask, v, bv, attn);
    softmax_kernel<<<Bb, 256>>>(attn);
    {
        dim3 grid(16, Bb);
        context_partial_kernel<<<grid, 512>>>(keys, attn);
    }
    context_reduce_kernel<<<Bb, Ee>>>(ctx);
}

// round 12
// speedup vs baseline: 1.5388x; 1.0812x over previous
#include <cuda_runtime.h>
#include <cuda_fp16.h>
#include <cstdint>

#define Bb 32
#define Ss 4096
#define Hh 512
#define Ee 512
#define NEGV -1000000000.0f

// ---------------- scratch ----------------
__device__ float g_qpc[Bb * Hh];
__device__ float g_ctxpart[16 * Bb * Ee];
__device__ __align__(16) __half g_wkt_hi[Hh * Ee];   // Wk^T hi [h][e] fp16
__device__ __align__(16) __half g_wkt_lo[Hh * Ee];   // Wk^T lo [h][e] fp16
__device__ __align__(16) __half g_kh[Bb * Ss * Ee];  // keys fp16 (written in phase 0)

// ---------------- helpers ----------------
__device__ __forceinline__ uint32_t smem_u32(const void* p) {
    uint32_t a;
    asm("{ .reg .u64 t; cvta.to.shared.u64 t, %1; cvt.u32.u64 %0, t; }" : "=r"(a) : "l"(p));
    return a;
}
__device__ __forceinline__ uint32_t swz(uint32_t off) { return off ^ ((off >> 3) & 0x70); }

__device__ __forceinline__ float tanh_fast(float x) {
    float e = __expf(2.0f * x);
    return 1.0f - __fdividef(2.0f, e + 1.0f);
}
__device__ __forceinline__ void ldmx4(uint32_t& r0, uint32_t& r1, uint32_t& r2, uint32_t& r3,
                                      uint32_t addr) {
    asm volatile("ldmatrix.sync.aligned.m8n8.x4.shared.b16 {%0,%1,%2,%3}, [%4];"
                 : "=r"(r0), "=r"(r1), "=r"(r2), "=r"(r3) : "r"(addr));
}
__device__ __forceinline__ void mma16816(float* d, const uint32_t* a, uint32_t b0, uint32_t b1) {
    asm volatile(
        "mma.sync.aligned.m16n8k16.row.col.f32.f16.f16.f32 "
        "{%0,%1,%2,%3}, {%4,%5,%6,%7}, {%8,%9}, {%0,%1,%2,%3};"
        : "+f"(d[0]), "+f"(d[1]), "+f"(d[2]), "+f"(d[3])
        : "r"(a[0]), "r"(a[1]), "r"(a[2]), "r"(a[3]), "r"(b0), "r"(b1));
}
#define CP_ASYNC16(dst, src) \
    asm volatile("cp.async.cg.shared.global [%0], [%1], 16;" :: "r"(dst), "l"(src))
#define CP_COMMIT() asm volatile("cp.async.commit_group;" ::: "memory")
#define CP_WAIT1() asm volatile("cp.async.wait_group 1;" ::: "memory")

// ---------------- K0: transpose+convert Wk -> fp16 hi/lo (Wkt[h][e]) ----------------
__global__ void wkt_kernel(const float* __restrict__ Wk) {
    __shared__ float t[64][65];
    int e0 = (blockIdx.x >> 3) * 64, h0 = (blockIdx.x & 7) * 64;
    int tx = threadIdx.x & 63, ty = threadIdx.x >> 6;
#pragma unroll
    for (int i = 0; i < 16; i++) {
        int r = ty + i * 4;
        t[r][tx] = Wk[(size_t)(e0 + r) * Hh + h0 + tx];
    }
    __syncthreads();
#pragma unroll
    for (int i = 0; i < 16; i++) {
        int hr = ty + i * 4;
        float x = t[tx][hr];
        __half hi = __float2half(x);
        __half lo = __float2half(x - __half2float(hi));
        g_wkt_hi[(size_t)(h0 + hr) * Ee + e0 + tx] = hi;
        g_wkt_lo[(size_t)(h0 + hr) * Ee + e0 + tx] = lo;
    }
}

// ---------------- K1: q_proj + bq + bk (128 blocks) ----------------
__global__ void qproj_kernel(const float* __restrict__ query, const float* __restrict__ Wq,
                             const float* __restrict__ bq, const float* __restrict__ bk) {
    __shared__ float qs[Hh];
    int b = blockIdx.x >> 2;
    int h = (blockIdx.x & 3) * 128 + threadIdx.x;
#pragma unroll
    for (int i = 0; i < 4; i++) qs[threadIdx.x + i * 128] = query[b * Hh + threadIdx.x + i * 128];
    __syncthreads();
    float acc = bq[h] + bk[h];
#pragma unroll 8
    for (int e = 0; e < Hh; e++) acc += qs[e] * Wq[e * Hh + h];
    g_qpc[b * Hh + h] = acc;
}

// ---------------- K2: mma.sync scores kernel (fp16 2-MMA split + writeback) ----------------
// CTA: M=128 x H via 4 N-phases of 128. 8 warps = 4(M) x 2(N), warp tile m32n64.
// Phase 0 (kc 0..7): raw fp32 A staged, converted to fp16 (smem + STG to g_kh).
// Phases 1-3: fp16 A cp.async'd DIRECTLY into the 3-ring A operand buffer. No convert.
#define MT 128
#define NP 128
#define KC 64
#define NIT 32                    // 4 phases x 8 k-chunks
#define O_ARAW 0                  // 2 x 32KB raw fp32 A (phase 0 only)
#define O_ACV 65536               // 3 x 16KB fp16 A ring
#define O_B 114688                // 2 x (Bh 16K | Bl 16K)
#define O_SQ 180224
#define O_SV (O_SQ + 2048)
#define O_RED (O_SV + 2048)
#define SMEM_TOTAL (O_RED + 1024)

__device__ __forceinline__ void issue_stage(uint32_t smem_base, const float* __restrict__ keys,
                                            int row0, int t) {
    const int tid = threadIdx.x;
    const int p = t >> 3, kc = t & 7;
    const int st = t & 1;
    // B: 128 n x 64 k fp16 hi/lo, 1024 x 16B each, 4/thread each
    const uint32_t bh = smem_base + O_B + st * 32768;
    const uint32_t bl = bh + 16384;
#pragma unroll
    for (int j = 0; j < 4; j++) {
        int s = tid + j * 256;
        int n = s >> 3, k8 = (s & 7) * 8;
        size_t gidx = (size_t)(p * NP + n) * Ee + kc * KC + k8;
        uint32_t off = swz((uint32_t)(n * 128 + k8 * 2));
        CP_ASYNC16(bh + off, (const char*)(g_wkt_hi + gidx));
        CP_ASYNC16(bl + off, (const char*)(g_wkt_lo + gidx));
    }
    if (t < 8) {
        // raw A fp32: 2048 x 16B, 8/thread
        const uint32_t araw = smem_base + O_ARAW + st * 32768;
#pragma unroll
        for (int j = 0; j < 8; j++) {
            int s = tid + j * 256;
            int r = s >> 4, kq = (s & 15) * 4;
            const char* src = (const char*)(keys + (size_t)(row0 + r) * Ee + kc * KC + kq);
            CP_ASYNC16(araw + r * 256 + kq * 4, src);
        }
    } else {
        // fp16 A direct into ring slot t%3: 1024 x 16B, 4/thread
        const uint32_t acv = smem_base + O_ACV + (t % 3) * 16384;
#pragma unroll
        for (int j = 0; j < 4; j++) {
            int s = tid + j * 256;
            int r = s >> 3, k8 = (s & 7) * 8;
            const char* src = (const char*)(g_kh + (size_t)(row0 + r) * Ee + kc * KC + k8);
            CP_ASYNC16(acv + swz((uint32_t)(r * 128 + k8 * 2)), src);
        }
    }
}

__device__ __forceinline__ void convert_A(char* smem, int row0, int t) {
    const int tid = threadIdx.x;
    const int st = t & 1;
    const int kc = t & 7;
    const char* raw = smem + O_ARAW + st * 32768;
    char* Ac = smem + O_ACV + (t % 3) * 16384;
#pragma unroll
    for (int j = 0; j < 4; j++) {
        int s = tid + j * 256;
        int r = s >> 3, k8 = (s & 7) * 8;
        const float4* rp = (const float4*)(raw + r * 256 + k8 * 4);
        float4 x0 = rp[0], x1 = rp[1];
        union { uint4 u; __half b[8]; } vc;
        vc.b[0] = __float2half(x0.x); vc.b[1] = __float2half(x0.y);
        vc.b[2] = __float2half(x0.z); vc.b[3] = __float2half(x0.w);
        vc.b[4] = __float2half(x1.x); vc.b[5] = __float2half(x1.y);
        vc.b[6] = __float2half(x1.z); vc.b[7] = __float2half(x1.w);
        *(uint4*)(Ac + swz((uint32_t)(r * 128 + k8 * 2))) = vc.u;
        *(uint4*)(g_kh + (size_t)(row0 + r) * Ee + kc * KC + k8) = vc.u;  // writeback
    }
}

__global__ __launch_bounds__(256, 1) void scores_mma_kernel(
    const float* __restrict__ keys, const int* __restrict__ mask,
    const float* __restrict__ v, const float* __restrict__ bv,
    float* __restrict__ scores) {
    extern __shared__ char smem[];
    const uint32_t smem_base = smem_u32(smem);
    const int tid = threadIdx.x;
    const int lane = tid & 31;
    const int wid = tid >> 5;
    const int wm = wid >> 1;          // 0..3
    const int wn = wid & 1;           // 0..1
    const int m_off = wm * 32;
    const int n_off = wn * 64;
    const int row0 = blockIdx.x * MT;
    const int b = row0 >> 12;

    float* sq = (float*)(smem + O_SQ);
    float* sv = (float*)(smem + O_SV);
    sq[tid] = g_qpc[b * Hh + tid];
    sq[tid + 256] = g_qpc[b * Hh + tid + 256];
    sv[tid] = v[tid];
    sv[tid + 256] = v[tid + 256];

    const int jm = lane >> 3;
    const int rr = lane & 7;

    float rs[4] = {0.f, 0.f, 0.f, 0.f};
    float acc[2][8][4];
#pragma unroll
    for (int f = 0; f < 2; f++)
#pragma unroll
        for (int j = 0; j < 8; j++)
#pragma unroll
            for (int q = 0; q < 4; q++) acc[f][j][q] = 0.f;

    // prologue: stage chunks 0,1; convert chunk 0 (+writeback)
    issue_stage(smem_base, keys, row0, 0);
    CP_COMMIT();
    issue_stage(smem_base, keys, row0, 1);
    CP_COMMIT();
    CP_WAIT1();
    __syncthreads();
    convert_A(smem, row0, 0);
    __syncthreads();

    for (int it = 0; it < NIT; it++) {
        const int p = it >> 3, kc = it & 7;
        const uint32_t a_base = smem_base + O_ACV + (it % 3) * 16384;
        const uint32_t bh_base = smem_base + O_B + (it & 1) * 32768;
        const uint32_t bl_base = bh_base + 16384;

        // ---- MMAs on chunk it ----
#pragma unroll
        for (int kk = 0; kk < 4; kk++) {
            const int k0l = kk * 16;
            uint32_t af[2][4];
#pragma unroll
            for (int f = 0; f < 2; f++) {
                uint32_t aoff = swz((uint32_t)((m_off + f * 16 + (jm & 1) * 8 + rr) * 128 +
                                               (k0l + (jm >> 1) * 8) * 2));
                ldmx4(af[f][0], af[f][1], af[f][2], af[f][3], a_base + aoff);
            }
#pragma unroll
            for (int q = 0; q < 4; q++) {
                const int frag0 = 2 * q;
                uint32_t boff = swz((uint32_t)((n_off + (frag0 + (jm >> 1)) * 8 + rr) * 128 +
                                               (k0l + (jm & 1) * 8) * 2));
                uint32_t bh0, bh1, bh2, bh3, bl0, bl1, bl2, bl3;
                ldmx4(bh0, bh1, bh2, bh3, bh_base + boff);
                ldmx4(bl0, bl1, bl2, bl3, bl_base + boff);
#pragma unroll
                for (int f = 0; f < 2; f++) {
                    mma16816(acc[f][frag0], af[f], bh0, bh1);
                    mma16816(acc[f][frag0], af[f], bl0, bl1);
                    mma16816(acc[f][frag0 + 1], af[f], bh2, bh3);
                    mma16816(acc[f][frag0 + 1], af[f], bl2, bl3);
                }
            }
        }
        __syncthreads();                      // stage (it) fully consumed

        // ---- issue loads for chunk it+2 ----
        if (it + 2 < NIT) issue_stage(smem_base, keys, row0, it + 2);
        CP_COMMIT();

        // ---- wait arrival of chunk it+1 ----
        if (it + 1 < NIT) {
            CP_WAIT1();
            __syncthreads();
        }
        // ---- phase 0 only: convert raw(it+1) -> fp16 (+writeback) ----
        if (it + 1 < 8) {
            convert_A(smem, row0, it + 1);
            __syncthreads();
        }

        // ---- end of phase: fold accumulators into row sums ----
        if (kc == 7) {
#pragma unroll
            for (int f = 0; f < 2; f++)
#pragma unroll
                for (int j = 0; j < 8; j++) {
                    const int col = p * NP + n_off + j * 8 + (lane & 3) * 2;
                    const float q0 = sq[col], q1 = sq[col + 1];
                    const float v0 = sv[col], v1 = sv[col + 1];
                    rs[f * 2 + 0] += tanh_fast(acc[f][j][0] + q0) * v0 +
                                     tanh_fast(acc[f][j][1] + q1) * v1;
                    rs[f * 2 + 1] += tanh_fast(acc[f][j][2] + q0) * v0 +
                                     tanh_fast(acc[f][j][3] + q1) * v1;
                    acc[f][j][0] = acc[f][j][1] = acc[f][j][2] = acc[f][j][3] = 0.f;
                }
        }
    }

    // reduce across 4 lanes sharing a row, then across 2 N-warps
#pragma unroll
    for (int i = 0; i < 4; i++) {
        rs[i] += __shfl_xor_sync(~0u, rs[i], 1);
        rs[i] += __shfl_xor_sync(~0u, rs[i], 2);
    }
    float* red = (float*)(smem + O_RED);   // [128][2]
    if ((lane & 3) == 0) {
#pragma unroll
        for (int i = 0; i < 4; i++) {
            int r = m_off + (i >> 1) * 16 + (i & 1) * 8 + (lane >> 2);
            red[r * 2 + wn] = rs[i];
        }
    }
    __syncthreads();
    if (tid < MT) {
        float s = red[tid * 2] + red[tid * 2 + 1] + bv[0];
        int grow = row0 + tid;
        s = (mask[grow] == 0) ? NEGV : s;
        scores[grow] = s;
    }
}

// ---------------- K3: softmax ----------------
__global__ void softmax_kernel(float* __restrict__ attn) {
    __shared__ float buf[Ss];
    __shared__ float rtmp[32];
    __shared__ float rowstat;
    int b = blockIdx.x, tid = threadIdx.x;
    float* row = attn + (size_t)b * Ss;
    float lmax = -3.4e38f;
#pragma unroll
    for (int i = 0; i < Ss / 256; i++) {
        float x = row[tid + i * 256];
        buf[tid + i * 256] = x;
        lmax = fmaxf(lmax, x);
    }
#pragma unroll
    for (int o = 16; o; o >>= 1) lmax = fmaxf(lmax, __shfl_xor_sync(~0u, lmax, o));
    if ((tid & 31) == 0) rtmp[tid >> 5] = lmax;
    __syncthreads();
    if (tid == 0) {
        float m = rtmp[0];
        for (int w = 1; w < 8; w++) m = fmaxf(m, rtmp[w]);
        rowstat = m;
    }
    __syncthreads();
    float m = rowstat;
    float lsum = 0.0f;
#pragma unroll
    for (int i = 0; i < Ss / 256; i++) {
        float e = __expf(buf[tid + i * 256] - m);
        buf[tid + i * 256] = e;
        lsum += e;
    }
#pragma unroll
    for (int o = 16; o; o >>= 1) lsum += __shfl_xor_sync(~0u, lsum, o);
    __syncthreads();
    if ((tid & 31) == 0) rtmp[tid >> 5] = lsum;
    __syncthreads();
    if (tid == 0) {
        float s = 0.0f;
        for (int w = 0; w < 8; w++) s += rtmp[w];
        rowstat = 1.0f / s;
    }
    __syncthreads();
    float inv = rowstat;
#pragma unroll
    for (int i = 0; i < Ss / 256; i++) row[tid + i * 256] = buf[tid + i * 256] * inv;
}

// ---------------- K4/K5: context ----------------
__global__ void context_partial_kernel(const float* __restrict__ keys,
                                       const float* __restrict__ attn) {
    __shared__ float aw[256];
    int b = blockIdx.y, chunk = blockIdx.x;   // 16 chunks of 256
    int s0 = chunk * 256;
    int tid = threadIdx.x;                    // 512
    if (tid < 256) aw[tid] = attn[(size_t)b * Ss + s0 + tid];
    __syncthreads();
    const float* kp = keys + ((size_t)b * Ss + s0) * Ee + tid;
    float acc = 0.0f;
#pragma unroll 8
    for (int s = 0; s < 256; s++) acc += aw[s] * kp[(size_t)s * Ee];
    g_ctxpart[(chunk * Bb + b) * Ee + tid] = acc;
}

__global__ void context_reduce_kernel(float* __restrict__ ctx) {
    int b = blockIdx.x, e = threadIdx.x;
    float acc = 0.0f;
#pragma unroll
    for (int c = 0; c < 16; c++) acc += g_ctxpart[(c * Bb + b) * Ee + e];
    ctx[b * Ee + e] = acc;
}

extern "C" void kernel_launch(void* const* d_in, const int* in_sizes, int n_in,
                              void* d_out, int out_size) {
    const float* query = (const float*)d_in[0];
    const float* keys  = (const float*)d_in[1];
    const int*   mask  = (const int*)d_in[2];
    const float* Wq    = (const float*)d_in[3];
    const float* bq    = (const float*)d_in[4];
    const float* Wk    = (const float*)d_in[5];
    const float* bk    = (const float*)d_in[6];
    const float* v     = (const float*)d_in[7];
    const float* bv    = (const float*)d_in[8];

    float* out  = (float*)d_out;
    float* ctx  = out;
    float* attn = out + Bb * Ee;

    cudaFuncSetAttribute(scores_mma_kernel, cudaFuncAttributeMaxDynamicSharedMemorySize,
                         SMEM_TOTAL);

    wkt_kernel<<<64, 256>>>(Wk);
    qproj_kernel<<<Bb * 4, 128>>>(query, Wq, bq, bk);
    scores_mma_kernel<<<(Bb * Ss) / MT, 256, SMEM_TOTAL>>>(keys, mask, v, bv, attn);
    softmax_kernel<<<Bb, 256>>>(attn);
    {
        dim3 grid(16, Bb);
        context_partial_kernel<<<grid, 512>>>(keys, attn);
    }
    context_reduce_kernel<<<Bb, Ee>>>(ctx);
}